// round 14
// baseline (speedup 1.0000x reference)
#include <cuda_runtime.h>
#include <cuda_fp16.h>
#include <math.h>
#include <stdint.h>

#define NTOK 2048
#define DDIM 1024
#define FDIM 4096
#define NEXP 8
#define NLAY 6
#define RTOT (NTOK*2)
#define MAXF 256
#define TAU  2e-4f
#define KSPL 4

// ---------------- scratch ----------------
__device__ uint32_t g_xnh[NTOK*DDIM/2];          // pre-split xn hi (half2, perm layout)
__device__ uint32_t g_xnl[NTOK*DDIM/2];          // lo
__device__ uint32_t g_Hh[(size_t)RTOT*FDIM/2];   // pre-split H hi
__device__ uint32_t g_Hl[(size_t)RTOT*FDIM/2];   // lo
__device__ float g_probs[NTOK*NEXP];
__device__ int   g_topi[RTOT];
__device__ float g_topv[RTOT];
__device__ int   g_cnt[NEXP], g_off[NEXP];
__device__ int   g_row_tok[RTOT];
__device__ int   g_tok_row[RTOT];
__device__ float g_Yp[(size_t)KSPL*RTOT*DDIM];   // split-K partials for GEMM2
__device__ float g_loss;
// exact-recompute scratch
__device__ int   g_flag[NTOK];
__device__ int   g_flist[MAXF];
__device__ int   g_F;
__device__ float ex_x [MAXF*DDIM];
__device__ float ex_xn[MAXF*DDIM];
__device__ float ex_h [(size_t)MAXF*2*FDIM];
__device__ float ex_y [(size_t)MAXF*2*DDIM];
__device__ int   ex_topi[MAXF*2];
__device__ float ex_topv[MAXF*2];

__device__ __forceinline__ void mma16(float* d, const uint32_t* a, uint32_t b0, uint32_t b1){
    asm volatile("mma.sync.aligned.m16n8k16.row.col.f32.f16.f16.f32 "
        "{%0,%1,%2,%3}, {%4,%5,%6,%7}, {%8,%9}, {%0,%1,%2,%3};"
        : "+f"(d[0]), "+f"(d[1]), "+f"(d[2]), "+f"(d[3])
        : "r"(a[0]), "r"(a[1]), "r"(a[2]), "r"(a[3]), "r"(b0), "r"(b1));
}
__device__ __forceinline__ void split2(float x, float y, uint32_t& hi, uint32_t& lo){
    __half2 h = __floats2half2_rn(x, y);
    float hx = __low2float(h), hy = __high2float(h);
    __half2 l = __floats2half2_rn(x - hx, y - hy);
    hi = *reinterpret_cast<uint32_t*>(&h);
    lo = *reinterpret_cast<uint32_t*>(&l);
}
// permuted position within each 8-wide k2 group: pairs (l, l+4) become adjacent
__device__ __forceinline__ uint32_t permk2(uint32_t k2){
    return (k2 & ~7u) | (((k2 & 3u) << 1) | ((k2 >> 2) & 1u));
}
__device__ __forceinline__ float gelu_tanh(float x){
    float x3 = x*x*x;
    float t  = tanhf(0.7978845608028654f*(x + 0.044715f*x3));
    return 0.5f*x*(1.0f+t);
}

// ---------------- fused LN + router + split-write (margin flag) ----------------
__global__ void lnrouter_kernel(const float* __restrict__ xin, const float* __restrict__ wr,
                                int first){
    int t = blockIdx.x, tid = threadIdx.x;
    __shared__ float red[256];
    __shared__ float sx[DDIM];
    __shared__ float slog[NEXP];
    float v[4];
    #pragma unroll
    for (int q=0;q<4;q++) v[q] = xin[(size_t)t*DDIM + q*256 + tid];
    float s = v[0]+v[1]+v[2]+v[3];
    red[tid]=s; __syncthreads();
    for (int o=128;o>0;o>>=1){ if(tid<o) red[tid]+=red[tid+o]; __syncthreads(); }
    float mean = red[0]*(1.0f/DDIM);
    __syncthreads();
    float s2=0.f;
    #pragma unroll
    for (int q=0;q<4;q++){ v[q]-=mean; s2 += v[q]*v[q]; }
    red[tid]=s2; __syncthreads();
    for (int o=128;o>0;o>>=1){ if(tid<o) red[tid]+=red[tid+o]; __syncthreads(); }
    float inv = 1.0f/sqrtf(red[0]*(1.0f/DDIM) + 1e-5f);
    #pragma unroll
    for (int q=0;q<4;q++) sx[q*256 + tid] = v[q]*inv;
    __syncthreads();
    // split-write xn (hi/lo half2, perm layout)
    #pragma unroll
    for (int j=0;j<2;j++){
        uint32_t k2 = tid + j*256;
        float a = sx[2*k2], b = sx[2*k2+1];
        uint32_t h,l; split2(a,b,h,l);
        uint32_t p = permk2(k2);
        g_xnh[(size_t)t*(DDIM/2) + p] = h;
        g_xnl[(size_t)t*(DDIM/2) + p] = l;
    }
    int e = tid>>5, lane = tid&31;
    float acc = 0.f;
    for (int d=lane; d<DDIM; d+=32) acc += sx[d]*wr[d*NEXP+e];
    #pragma unroll
    for (int o=16;o>0;o>>=1) acc += __shfl_down_sync(0xffffffffu, acc, o);
    if (lane==0) slog[e]=acc;
    __syncthreads();
    if (tid==0){
        float p[NEXP];
        float m = slog[0];
        #pragma unroll
        for (int i=1;i<NEXP;i++) m = fmaxf(m, slog[i]);
        float ssum = 0.f;
        #pragma unroll
        for (int i=0;i<NEXP;i++){ p[i]=expf(slog[i]-m); ssum+=p[i]; }
        #pragma unroll
        for (int i=0;i<NEXP;i++){ p[i] = p[i]/ssum; g_probs[t*NEXP+i]=p[i]; }
        int i1=0; float v1=p[0];
        #pragma unroll
        for (int i=1;i<NEXP;i++) if (p[i]>v1){ v1=p[i]; i1=i; }
        int i2=-1; float v2=-1e30f;
        #pragma unroll
        for (int i=0;i<NEXP;i++) if (i!=i1 && p[i]>v2){ v2=p[i]; i2=i; }
        float v3=-1e30f;
        #pragma unroll
        for (int i=0;i<NEXP;i++) if (i!=i1 && i!=i2 && p[i]>v3) v3=p[i];
        int c = (v2 - v3 < TAU) ? 1 : 0;
        if (first) g_flag[t] = c;
        else if (c) g_flag[t] = 1;
        g_topi[t*2+0]=i1; g_topv[t*2+0]=v1;
        g_topi[t*2+1]=i2; g_topv[t*2+1]=v2;
    }
}

// ---------------- stats + placement (single block) ----------------
__global__ void statsplace_kernel(int first){
    int tid = threadIdx.x;                 // 1024 threads
    __shared__ int   sc[NEXP];
    __shared__ int   scur[NEXP];
    __shared__ int   soff[NEXP];
    __shared__ float red[1024];
    __shared__ float sexp[NEXP];
    if (tid<NEXP){ sc[tid]=0; scur[tid]=0; }
    __syncthreads();
    for (int i=tid;i<RTOT;i+=1024) atomicAdd(&sc[g_topi[i]], 1);
    float myp[NEXP];
    #pragma unroll
    for (int e=0;e<NEXP;e++) myp[e]=0.f;
    for (int t=tid;t<NTOK;t+=1024){
        #pragma unroll
        for (int e=0;e<NEXP;e++) myp[e] += g_probs[t*NEXP+e];
    }
    __syncthreads();
    for (int e=0;e<NEXP;e++){
        red[tid]=myp[e]; __syncthreads();
        for (int o=512;o>0;o>>=1){ if(tid<o) red[tid]+=red[tid+o]; __syncthreads(); }
        if (tid==0) sexp[e]=red[0];
        __syncthreads();
    }
    if (tid==0){
        float loss=0.f; int off=0;
        #pragma unroll
        for (int e=0;e<NEXP;e++){
            loss += ((float)sc[e]*(1.0f/NTOK)) * (sexp[e]*(1.0f/NTOK));
            g_cnt[e]=sc[e]; g_off[e]=off; soff[e]=off; off+=sc[e];
        }
        if (first){ g_loss = (float)NEXP*loss; g_F = 0; }
        else        g_loss += (float)NEXP*loss;
    }
    __syncthreads();
    for (int i=tid;i<RTOT;i+=1024){
        int e = g_topi[i];
        int r = soff[e] + atomicAdd(&scur[e], 1);
        g_row_tok[r] = i>>1;
        g_tok_row[i] = r;
    }
}

// ---------------- fp16x3 mma.sync grouped GEMM: A direct-global, B via SMEM ----------------
#define BPAD2 17
#define OFF_BH 0
#define OFF_BL 8704
#define BUF_SZ 17408
#define SM_TOTAL (512 + 2*BUF_SZ)

template<bool G1, int OCC, int KSP>
__global__ void __launch_bounds__(256, OCC) moe_gemm_h3(const float* __restrict__ W,
                                                        const float* __restrict__ bias){
    constexpr int KT  = G1 ? DDIM : FDIM;
    constexpr int K2  = KT/2;               // A row length in half2
    constexpr int LDW = G1 ? FDIM : DDIM;
    constexpr int S   = KT/16/KSP;

    extern __shared__ char smem[];
    int* sidx = (int*)smem;
    char* bufbase = smem + 512;

    int e = blockIdx.z;
    int cnt = g_cnt[e];
    int ks = 0, my = blockIdx.y;
    if (KSP > 1){ ks = my & (KSP-1); my >>= 2; }
    int m0 = my*128;
    if (m0 >= cnt) return;
    int off = g_off[e];
    int n0 = blockIdx.x*128;
    int kbase  = ks*(KT/KSP);
    int kbase2 = kbase/2;
    int tid = threadIdx.x, w = tid>>5, lane = tid&31;
    int g = lane>>2, tig = lane&3;
    int mw = (w&1)*64, nw = (w>>1)*32;

    const uint32_t* AH = G1 ? g_xnh : g_Hh;
    const uint32_t* AL = G1 ? g_xnl : g_Hl;

    if (tid < 128){
        int i = m0 + tid; if (i >= cnt) i = cnt-1;
        sidx[tid] = G1 ? g_row_tok[off+i] : (off+i);
    }
    __syncthreads();

    // per-thread A row offsets (element units in half2 arrays)
    uint32_t ro0[4], ro1[4];
    #pragma unroll
    for (int mf=0;mf<4;mf++){
        ro0[mf] = (uint32_t)sidx[mw + mf*16 + g]     * K2;
        ro1[mf] = (uint32_t)sidx[mw + mf*16 + g + 8] * K2;
    }

    int kp = tid>>6;
    int n2 = (tid&63)*2;
    const float* bptr = W + (size_t)e*KT*LDW + (size_t)kbase*LDW + n0 + n2;
    const float* biasp = bias + (size_t)e*LDW + n0;

    float2 q00, q01, q10, q11;
    auto LOADS = [&](int s){
        int k0 = s*16;
        q00 = *(const float2*)(bptr + (size_t)(k0 + 2*kp    )*LDW);
        q01 = *(const float2*)(bptr + (size_t)(k0 + 2*kp + 1)*LDW);
        q10 = *(const float2*)(bptr + (size_t)(k0 + 2*kp + 8)*LDW);
        q11 = *(const float2*)(bptr + (size_t)(k0 + 2*kp + 9)*LDW);
    };
    auto STORES = [&](int b){
        char* bb = bufbase + b*BUF_SZ;
        uint32_t* Bh = (uint32_t*)(bb + OFF_BH);
        uint32_t* Bl = (uint32_t*)(bb + OFF_BL);
        uint32_t h,l;
        split2(q00.x, q01.x, h, l); Bh[ n2   *BPAD2 + kp    ] = h; Bl[ n2   *BPAD2 + kp    ] = l;
        split2(q00.y, q01.y, h, l); Bh[(n2+1)*BPAD2 + kp    ] = h; Bl[(n2+1)*BPAD2 + kp    ] = l;
        split2(q10.x, q11.x, h, l); Bh[ n2   *BPAD2 + kp + 4] = h; Bl[ n2   *BPAD2 + kp + 4] = l;
        split2(q10.y, q11.y, h, l); Bh[(n2+1)*BPAD2 + kp + 4] = h; Bl[(n2+1)*BPAD2 + kp + 4] = l;
    };

    float acc[4][4][4] = {};
    auto COMPUTE = [&](int b, int kk2){
        char* bb = bufbase + b*BUF_SZ;
        const uint32_t* Bh = (const uint32_t*)(bb + OFF_BH);
        const uint32_t* Bl = (const uint32_t*)(bb + OFF_BL);
        uint32_t afh[4][4], afl[4][4];
        int ka = kk2 + tig*2;
        #pragma unroll
        for (int mf=0;mf<4;mf++){
            uint2 h0 = *(const uint2*)(AH + ro0[mf] + ka);   // a0, a2
            uint2 h1 = *(const uint2*)(AH + ro1[mf] + ka);   // a1, a3
            afh[mf][0]=h0.x; afh[mf][1]=h1.x; afh[mf][2]=h0.y; afh[mf][3]=h1.y;
            uint2 l0 = *(const uint2*)(AL + ro0[mf] + ka);
            uint2 l1 = *(const uint2*)(AL + ro1[mf] + ka);
            afl[mf][0]=l0.x; afl[mf][1]=l1.x; afl[mf][2]=l0.y; afl[mf][3]=l1.y;
        }
        #pragma unroll
        for (int nf=0;nf<4;nf++){
            int n = nw + nf*8 + g;
            uint32_t bh0 = Bh[n*BPAD2 + tig];
            uint32_t bh1 = Bh[n*BPAD2 + tig + 4];
            uint32_t bl0 = Bl[n*BPAD2 + tig];
            uint32_t bl1 = Bl[n*BPAD2 + tig + 4];
            #pragma unroll
            for (int mf=0;mf<4;mf++){
                mma16(acc[mf][nf], afh[mf], bh0, bh1);   // hi*hi
                mma16(acc[mf][nf], afl[mf], bh0, bh1);   // lo*hi
                mma16(acc[mf][nf], afh[mf], bl0, bl1);   // hi*lo
            }
        }
    };

    LOADS(0);
    STORES(0);
    __syncthreads();
    for (int s=0;s<S;s++){
        if (s+1 < S) LOADS(s+1);
        COMPUTE(s&1, kbase2 + s*8);
        if (s+1 < S){
            STORES((s+1)&1);
            __syncthreads();
        }
    }

    #pragma unroll
    for (int mf=0;mf<4;mf++){
        int r0 = m0 + mw + mf*16 + g;
        int r1 = r0 + 8;
        #pragma unroll
        for (int nf=0;nf<4;nf++){
            int col = nw + nf*8 + tig*2;
            if (G1){
                // write split H (hi/lo half2, perm layout)
                uint32_t k2 = (uint32_t)(n0 + col) >> 1;
                uint32_t p = permk2(k2);
                if (r0 < cnt){
                    float ox = gelu_tanh(acc[mf][nf][0] + biasp[col]);
                    float oy = gelu_tanh(acc[mf][nf][1] + biasp[col+1]);
                    uint32_t h,l; split2(ox, oy, h, l);
                    g_Hh[(size_t)(off+r0)*(LDW/2) + p] = h;
                    g_Hl[(size_t)(off+r0)*(LDW/2) + p] = l;
                }
                if (r1 < cnt){
                    float ox = gelu_tanh(acc[mf][nf][2] + biasp[col]);
                    float oy = gelu_tanh(acc[mf][nf][3] + biasp[col+1]);
                    uint32_t h,l; split2(ox, oy, h, l);
                    g_Hh[(size_t)(off+r1)*(LDW/2) + p] = h;
                    g_Hl[(size_t)(off+r1)*(LDW/2) + p] = l;
                }
            } else {
                float* Outp = g_Yp + (size_t)ks*RTOT*DDIM;
                if (r0 < cnt){
                    float2 o;
                    o.x = acc[mf][nf][0];
                    o.y = acc[mf][nf][1];
                    *(float2*)(Outp + (size_t)(off+r0)*LDW + n0 + col) = o;
                }
                if (r1 < cnt){
                    float2 o;
                    o.x = acc[mf][nf][2];
                    o.y = acc[mf][nf][3];
                    *(float2*)(Outp + (size_t)(off+r1)*LDW + n0 + col) = o;
                }
            }
        }
    }
}

// ---------------- combine: split-K reduction + bias + gated residual (+init on first) ----------------
__global__ void combine_kernel(float* __restrict__ out, const float* __restrict__ b2l,
                               const float* __restrict__ x, int first){
    int t = blockIdx.x, tid = threadIdx.x;
    int r1 = g_tok_row[t*2+0], r2 = g_tok_row[t*2+1];
    float g1 = g_topv[t*2+0],  g2 = g_topv[t*2+1];
    int e1 = g_topi[t*2+0],    e2 = g_topi[t*2+1];
    const float* p0 = g_Yp;
    #pragma unroll
    for (int q=0;q<4;q++){
        int d = q*256 + tid;
        float y1 = p0[((size_t)0*RTOT + r1)*DDIM + d]
                 + p0[((size_t)1*RTOT + r1)*DDIM + d]
                 + p0[((size_t)2*RTOT + r1)*DDIM + d]
                 + p0[((size_t)3*RTOT + r1)*DDIM + d]
                 + b2l[(size_t)e1*DDIM + d];
        float y2 = p0[((size_t)0*RTOT + r2)*DDIM + d]
                 + p0[((size_t)1*RTOT + r2)*DDIM + d]
                 + p0[((size_t)2*RTOT + r2)*DDIM + d]
                 + p0[((size_t)3*RTOT + r2)*DDIM + d]
                 + b2l[(size_t)e2*DDIM + d];
        float base = first ? x[(size_t)t*DDIM + d] : out[(size_t)t*DDIM + d];
        out[(size_t)t*DDIM + d] = base + g1*y1 + g2*y2;
    }
}
__global__ void finish_kernel(float* __restrict__ out){
    out[(size_t)NTOK*DDIM] = g_loss;
}

// ================= exact-recompute path (bitwise-R1 for flagged tokens) =================
__global__ void flist_kernel(){
    int t = blockIdx.x*blockDim.x + threadIdx.x;
    if (t < NTOK && g_flag[t]){
        int pos = atomicAdd(&g_F, 1);
        if (pos < MAXF) g_flist[pos] = t;
    }
}
__global__ void ex_init_kernel(const float* __restrict__ x){
    int b = blockIdx.x;
    if (b >= g_F || b >= MAXF) return;
    int t = g_flist[b], tid = threadIdx.x;
    #pragma unroll
    for (int q=0;q<4;q++)
        ex_x[b*DDIM + q*256 + tid] = x[(size_t)t*DDIM + q*256 + tid];
}
__global__ void ex_ln_kernel(){
    int b = blockIdx.x;
    if (b >= g_F || b >= MAXF) return;
    int tid = threadIdx.x;
    __shared__ float red[256];
    float v[4];
    #pragma unroll
    for (int q=0;q<4;q++) v[q] = ex_x[b*DDIM + q*256 + tid];
    float s = v[0]+v[1]+v[2]+v[3];
    red[tid]=s; __syncthreads();
    for (int o=128;o>0;o>>=1){ if(tid<o) red[tid]+=red[tid+o]; __syncthreads(); }
    float mean = red[0]*(1.0f/DDIM);
    __syncthreads();
    float s2=0.f;
    #pragma unroll
    for (int q=0;q<4;q++){ v[q]-=mean; s2 += v[q]*v[q]; }
    red[tid]=s2; __syncthreads();
    for (int o=128;o>0;o>>=1){ if(tid<o) red[tid]+=red[tid+o]; __syncthreads(); }
    float inv = 1.0f/sqrtf(red[0]*(1.0f/DDIM) + 1e-5f);
    #pragma unroll
    for (int q=0;q<4;q++) ex_xn[b*DDIM + q*256 + tid] = v[q]*inv;
}
__global__ void ex_router_kernel(const float* __restrict__ wr){
    int b = blockIdx.x;
    if (b >= g_F || b >= MAXF) return;
    int tid = threadIdx.x;
    __shared__ float sx[DDIM];
    __shared__ float slog[NEXP];
    #pragma unroll
    for (int q=0;q<4;q++) sx[q*256+tid] = ex_xn[b*DDIM + q*256 + tid];
    __syncthreads();
    int e = tid>>5, lane = tid&31;
    float acc = 0.f;
    for (int d=lane; d<DDIM; d+=32) acc += sx[d]*wr[d*NEXP+e];
    #pragma unroll
    for (int o=16;o>0;o>>=1) acc += __shfl_down_sync(0xffffffffu, acc, o);
    if (lane==0) slog[e]=acc;
    __syncthreads();
    if (tid==0){
        float p[NEXP];
        float m = slog[0];
        #pragma unroll
        for (int i=1;i<NEXP;i++) m = fmaxf(m, slog[i]);
        float ssum = 0.f;
        #pragma unroll
        for (int i=0;i<NEXP;i++){ p[i]=expf(slog[i]-m); ssum+=p[i]; }
        #pragma unroll
        for (int i=0;i<NEXP;i++) p[i] = p[i]/ssum;
        int i1=0; float v1=p[0];
        #pragma unroll
        for (int i=1;i<NEXP;i++) if (p[i]>v1){ v1=p[i]; i1=i; }
        int i2=-1; float v2=-1e30f;
        #pragma unroll
        for (int i=0;i<NEXP;i++) if (i!=i1 && p[i]>v2){ v2=p[i]; i2=i; }
        ex_topi[b*2+0]=i1; ex_topv[b*2+0]=v1;
        ex_topi[b*2+1]=i2; ex_topv[b*2+1]=v2;
    }
}
__global__ void ex_gemm1_kernel(const float* __restrict__ w1l, const float* __restrict__ b1l){
    int b = blockIdx.z;
    if (b >= g_F || b >= MAXF) return;
    int slot = blockIdx.y, tid = threadIdx.x;
    int col = blockIdx.x*256 + tid;
    int e = ex_topi[b*2+slot];
    __shared__ float sxn[DDIM];
    #pragma unroll
    for (int q=0;q<4;q++) sxn[q*256+tid] = ex_xn[b*DDIM + q*256 + tid];
    __syncthreads();
    const float* wcol = w1l + (size_t)e*DDIM*FDIM + col;
    float acc = 0.f;
    #pragma unroll 8
    for (int k=0;k<DDIM;k++) acc = fmaf(sxn[k], wcol[(size_t)k*FDIM], acc);
    float bb = b1l[(size_t)e*FDIM + col];
    ex_h[((size_t)b*2+slot)*FDIM + col] = gelu_tanh(acc + bb);
}
__global__ void ex_gemm2_kernel(const float* __restrict__ w2l, const float* __restrict__ b2l){
    int b = blockIdx.z;
    if (b >= g_F || b >= MAXF) return;
    int slot = blockIdx.y, tid = threadIdx.x;
    int col = blockIdx.x*256 + tid;
    int e = ex_topi[b*2+slot];
    __shared__ float sh[FDIM];
    #pragma unroll
    for (int q=0;q<16;q++) sh[q*256+tid] = ex_h[((size_t)b*2+slot)*FDIM + q*256 + tid];
    __syncthreads();
    const float* wcol = w2l + (size_t)e*FDIM*DDIM + col;
    float acc = 0.f;
    #pragma unroll 8
    for (int k=0;k<FDIM;k++) acc = fmaf(sh[k], wcol[(size_t)k*DDIM], acc);
    float bb = b2l[(size_t)e*DDIM + col];
    ex_y[((size_t)b*2+slot)*DDIM + col] = acc + bb;
}
__global__ void ex_combine_kernel(){
    int b = blockIdx.x;
    if (b >= g_F || b >= MAXF) return;
    int tid = threadIdx.x;
    float g1 = ex_topv[b*2+0], g2 = ex_topv[b*2+1];
    const float* y1 = ex_y + ((size_t)b*2+0)*DDIM;
    const float* y2 = ex_y + ((size_t)b*2+1)*DDIM;
    #pragma unroll
    for (int q=0;q<4;q++){
        int d = q*256 + tid;
        ex_x[b*DDIM + d] += g1*y1[d] + g2*y2[d];
    }
}
__global__ void ex_write_kernel(float* __restrict__ out){
    int b = blockIdx.x;
    if (b >= g_F || b >= MAXF) return;
    int t = g_flist[b], tid = threadIdx.x;
    #pragma unroll
    for (int q=0;q<4;q++)
        out[(size_t)t*DDIM + q*256 + tid] = ex_x[b*DDIM + q*256 + tid];
}

// ---------------- launch ----------------
extern "C" void kernel_launch(void* const* d_in, const int* in_sizes, int n_in,
                              void* d_out, int out_size){
    const float* x  = (const float*)d_in[0];
    const float* wr = (const float*)d_in[1];
    const float* w1 = (const float*)d_in[2];
    const float* b1 = (const float*)d_in[3];
    const float* w2 = (const float*)d_in[4];
    const float* b2 = (const float*)d_in[5];
    float* out = (float*)d_out;

    cudaFuncSetAttribute((const void*)moe_gemm_h3<true,2,1>,     cudaFuncAttributeMaxDynamicSharedMemorySize, SM_TOTAL);
    cudaFuncSetAttribute((const void*)moe_gemm_h3<false,2,KSPL>, cudaFuncAttributeMaxDynamicSharedMemorySize, SM_TOTAL);

    // fast path (4th launch overall == gemm2 for ncu capture)
    for (int l=0;l<NLAY;l++){
        const float* wr_l = wr + (size_t)l*DDIM*NEXP;
        const float* w1_l = w1 + (size_t)l*NEXP*DDIM*FDIM;
        const float* b1_l = b1 + (size_t)l*NEXP*FDIM;
        const float* w2_l = w2 + (size_t)l*NEXP*FDIM*DDIM;
        const float* b2_l = b2 + (size_t)l*NEXP*DDIM;
        int first = (l==0);

        lnrouter_kernel  <<<NTOK, 256>>>(first ? x : out, wr_l, first);
        statsplace_kernel<<<1, 1024>>>(first);
        moe_gemm_h3<true,2,1>    <<<dim3(FDIM/128, 32, NEXP), 256, SM_TOTAL>>>(w1_l, b1_l);
        moe_gemm_h3<false,2,KSPL><<<dim3(DDIM/128, 32*KSPL, NEXP), 256, SM_TOTAL>>>(w2_l, b2_l);
        combine_kernel<<<NTOK, 256>>>(out, b2_l, x, first);
    }

    // exact recompute of flagged tokens (bitwise-R1)
    flist_kernel  <<<NTOK/256, 256>>>();
    ex_init_kernel<<<MAXF, 256>>>(x);
    for (int l=0;l<NLAY;l++){
        const float* wr_l = wr + (size_t)l*DDIM*NEXP;
        const float* w1_l = w1 + (size_t)l*NEXP*DDIM*FDIM;
        const float* b1_l = b1 + (size_t)l*NEXP*FDIM;
        const float* w2_l = w2 + (size_t)l*NEXP*FDIM*DDIM;
        const float* b2_l = b2 + (size_t)l*NEXP*DDIM;

        ex_ln_kernel    <<<MAXF, 256>>>();
        ex_router_kernel<<<MAXF, 256>>>(wr_l);
        ex_gemm1_kernel <<<dim3(FDIM/256, 2, MAXF), 256>>>(w1_l, b1_l);
        ex_gemm2_kernel <<<dim3(DDIM/256, 2, MAXF), 256>>>(w2_l, b2_l);
        ex_combine_kernel<<<MAXF, 256>>>();
    }
    ex_write_kernel<<<MAXF, 256>>>(out);

    if (out_size > NTOK*DDIM) finish_kernel<<<1,1>>>(out);
}

// round 15
// speedup vs baseline: 1.0822x; 1.0822x over previous
#include <cuda_runtime.h>
#include <cuda_fp16.h>
#include <math.h>
#include <stdint.h>

#define NTOK 2048
#define DDIM 1024
#define FDIM 4096
#define NEXP 8
#define NLAY 6
#define RTOT (NTOK*2)
#define MAXF 256
#define TAU  2e-4f
#define KSPL 4

// ---------------- scratch ----------------
__device__ float    g_xn[NTOK*DDIM];             // fp32 xn (gemm1 stages from here)
__device__ uint32_t g_Hh[(size_t)RTOT*FDIM/2];   // pre-split H hi (half2, perm layout)
__device__ uint32_t g_Hl[(size_t)RTOT*FDIM/2];   // lo
__device__ float g_probs[NTOK*NEXP];
__device__ int   g_topi[RTOT];
__device__ float g_topv[RTOT];
__device__ int   g_cnt[NEXP], g_off[NEXP];
__device__ int   g_row_tok[RTOT];
__device__ int   g_tok_row[RTOT];
__device__ float g_Yp[(size_t)KSPL*RTOT*DDIM];   // split-K partials for GEMM2
__device__ float g_loss;
// exact-recompute scratch
__device__ int   g_flag[NTOK];
__device__ int   g_flist[MAXF];
__device__ int   g_F;
__device__ float ex_x [MAXF*DDIM];
__device__ float ex_xn[MAXF*DDIM];
__device__ float ex_h [(size_t)MAXF*2*FDIM];
__device__ float ex_y [(size_t)MAXF*2*DDIM];
__device__ int   ex_topi[MAXF*2];
__device__ float ex_topv[MAXF*2];

__device__ __forceinline__ void mma16(float* d, const uint32_t* a, uint32_t b0, uint32_t b1){
    asm volatile("mma.sync.aligned.m16n8k16.row.col.f32.f16.f16.f32 "
        "{%0,%1,%2,%3}, {%4,%5,%6,%7}, {%8,%9}, {%0,%1,%2,%3};"
        : "+f"(d[0]), "+f"(d[1]), "+f"(d[2]), "+f"(d[3])
        : "r"(a[0]), "r"(a[1]), "r"(a[2]), "r"(a[3]), "r"(b0), "r"(b1));
}
__device__ __forceinline__ void split2(float x, float y, uint32_t& hi, uint32_t& lo){
    __half2 h = __floats2half2_rn(x, y);
    float hx = __low2float(h), hy = __high2float(h);
    __half2 l = __floats2half2_rn(x - hx, y - hy);
    hi = *reinterpret_cast<uint32_t*>(&h);
    lo = *reinterpret_cast<uint32_t*>(&l);
}
// permuted position within each 8-wide k2 group: fragment pairs (l, l+4) adjacent
__device__ __forceinline__ uint32_t permk2(uint32_t k2){
    return (k2 & ~7u) | (((k2 & 3u) << 1) | ((k2 >> 2) & 1u));
}
__device__ __forceinline__ float gelu_tanh(float x){
    float x3 = x*x*x;
    float t  = tanhf(0.7978845608028654f*(x + 0.044715f*x3));
    return 0.5f*x*(1.0f+t);
}

// ---------------- fused LN + router (margin flag; init fused via `first`) ----------------
__global__ void lnrouter_kernel(const float* __restrict__ xin, const float* __restrict__ wr,
                                int first){
    int t = blockIdx.x, tid = threadIdx.x;
    __shared__ float red[256];
    __shared__ float sx[DDIM];
    __shared__ float slog[NEXP];
    float v[4];
    #pragma unroll
    for (int q=0;q<4;q++) v[q] = xin[(size_t)t*DDIM + q*256 + tid];
    float s = v[0]+v[1]+v[2]+v[3];
    red[tid]=s; __syncthreads();
    for (int o=128;o>0;o>>=1){ if(tid<o) red[tid]+=red[tid+o]; __syncthreads(); }
    float mean = red[0]*(1.0f/DDIM);
    __syncthreads();
    float s2=0.f;
    #pragma unroll
    for (int q=0;q<4;q++){ v[q]-=mean; s2 += v[q]*v[q]; }
    red[tid]=s2; __syncthreads();
    for (int o=128;o>0;o>>=1){ if(tid<o) red[tid]+=red[tid+o]; __syncthreads(); }
    float inv = 1.0f/sqrtf(red[0]*(1.0f/DDIM) + 1e-5f);
    #pragma unroll
    for (int q=0;q<4;q++){
        float nv = v[q]*inv;
        g_xn[(size_t)t*DDIM + q*256 + tid] = nv;
        sx[q*256 + tid] = nv;
    }
    __syncthreads();
    int e = tid>>5, lane = tid&31;
    float acc = 0.f;
    for (int d=lane; d<DDIM; d+=32) acc += sx[d]*wr[d*NEXP+e];
    #pragma unroll
    for (int o=16;o>0;o>>=1) acc += __shfl_down_sync(0xffffffffu, acc, o);
    if (lane==0) slog[e]=acc;
    __syncthreads();
    if (tid==0){
        float p[NEXP];
        float m = slog[0];
        #pragma unroll
        for (int i=1;i<NEXP;i++) m = fmaxf(m, slog[i]);
        float ssum = 0.f;
        #pragma unroll
        for (int i=0;i<NEXP;i++){ p[i]=expf(slog[i]-m); ssum+=p[i]; }
        #pragma unroll
        for (int i=0;i<NEXP;i++){ p[i] = p[i]/ssum; g_probs[t*NEXP+i]=p[i]; }
        int i1=0; float v1=p[0];
        #pragma unroll
        for (int i=1;i<NEXP;i++) if (p[i]>v1){ v1=p[i]; i1=i; }
        int i2=-1; float v2=-1e30f;
        #pragma unroll
        for (int i=0;i<NEXP;i++) if (i!=i1 && p[i]>v2){ v2=p[i]; i2=i; }
        float v3=-1e30f;
        #pragma unroll
        for (int i=0;i<NEXP;i++) if (i!=i1 && i!=i2 && p[i]>v3) v3=p[i];
        int c = (v2 - v3 < TAU) ? 1 : 0;
        if (first) g_flag[t] = c;
        else if (c) g_flag[t] = 1;
        g_topi[t*2+0]=i1; g_topv[t*2+0]=v1;
        g_topi[t*2+1]=i2; g_topv[t*2+1]=v2;
    }
}

// ---------------- stats + placement (single block) ----------------
__global__ void statsplace_kernel(int first){
    int tid = threadIdx.x;                 // 1024 threads
    __shared__ int   sc[NEXP];
    __shared__ int   scur[NEXP];
    __shared__ int   soff[NEXP];
    __shared__ float red[1024];
    __shared__ float sexp[NEXP];
    if (tid<NEXP){ sc[tid]=0; scur[tid]=0; }
    __syncthreads();
    for (int i=tid;i<RTOT;i+=1024) atomicAdd(&sc[g_topi[i]], 1);
    float myp[NEXP];
    #pragma unroll
    for (int e=0;e<NEXP;e++) myp[e]=0.f;
    for (int t=tid;t<NTOK;t+=1024){
        #pragma unroll
        for (int e=0;e<NEXP;e++) myp[e] += g_probs[t*NEXP+e];
    }
    __syncthreads();
    for (int e=0;e<NEXP;e++){
        red[tid]=myp[e]; __syncthreads();
        for (int o=512;o>0;o>>=1){ if(tid<o) red[tid]+=red[tid+o]; __syncthreads(); }
        if (tid==0) sexp[e]=red[0];
        __syncthreads();
    }
    if (tid==0){
        float loss=0.f; int off=0;
        #pragma unroll
        for (int e=0;e<NEXP;e++){
            loss += ((float)sc[e]*(1.0f/NTOK)) * (sexp[e]*(1.0f/NTOK));
            g_cnt[e]=sc[e]; g_off[e]=off; soff[e]=off; off+=sc[e];
        }
        if (first){ g_loss = (float)NEXP*loss; g_F = 0; }
        else        g_loss += (float)NEXP*loss;
    }
    __syncthreads();
    for (int i=tid;i<RTOT;i+=1024){
        int e = g_topi[i];
        int r = soff[e] + atomicAdd(&scur[e], 1);
        g_row_tok[r] = i>>1;
        g_tok_row[i] = r;
    }
}

// ================= GEMM1: R13 SMEM-staged mainloop, split-H epilogue =================
#define APAD2 12
#define BPAD2 17
#define OFF_AH1 0
#define OFF_AL1 6144
#define OFF_BH1 12288
#define OFF_BL1 20992
#define BUF1_SZ 29696
#define SM1_TOTAL (512 + 2*BUF1_SZ)

__global__ void __launch_bounds__(256, 2) gemm1_kernel(const float* __restrict__ W,
                                                       const float* __restrict__ bias){
    constexpr int KT  = DDIM;
    constexpr int LDW = FDIM;
    constexpr int S   = KT/16;

    extern __shared__ char smem[];
    int* sidx = (int*)smem;
    char* bufbase = smem + 512;

    int e = blockIdx.z;
    int cnt = g_cnt[e];
    int m0 = blockIdx.y*128;
    if (m0 >= cnt) return;
    int off = g_off[e];
    int n0 = blockIdx.x*128;
    int tid = threadIdx.x, w = tid>>5, lane = tid&31;
    int g = lane>>2, tig = lane&3;
    int mw = (w&1)*64, nw = (w>>1)*32;

    if (tid < 128){
        int i = m0 + tid; if (i >= cnt) i = cnt-1;
        sidx[tid] = g_row_tok[off+i];
    }
    __syncthreads();

    const float* aptr0 = g_xn + (size_t)sidx[tid>>2]*KT + (tid&3)*4;
    const float* aptr1 = g_xn + (size_t)sidx[(tid>>2)+64]*KT + (tid&3)*4;
    int kp = tid>>6;
    int n2 = (tid&63)*2;
    const float* bptr = W + (size_t)e*KT*LDW + n0 + n2;
    const float* biasp = bias + (size_t)e*LDW + n0;

    float4 av[2];
    float2 q00, q01, q10, q11;
    auto LOADS = [&](int s){
        int k0 = s*16;
        av[0] = *(const float4*)(aptr0 + k0);
        av[1] = *(const float4*)(aptr1 + k0);
        q00 = *(const float2*)(bptr + (size_t)(k0 + 2*kp    )*LDW);
        q01 = *(const float2*)(bptr + (size_t)(k0 + 2*kp + 1)*LDW);
        q10 = *(const float2*)(bptr + (size_t)(k0 + 2*kp + 8)*LDW);
        q11 = *(const float2*)(bptr + (size_t)(k0 + 2*kp + 9)*LDW);
    };
    auto STORES = [&](int b){
        char* bb = bufbase + b*BUF1_SZ;
        uint32_t* Ah = (uint32_t*)(bb + OFF_AH1);
        uint32_t* Al = (uint32_t*)(bb + OFF_AL1);
        uint32_t* Bh = (uint32_t*)(bb + OFF_BH1);
        uint32_t* Bl = (uint32_t*)(bb + OFF_BL1);
        int kq = tid&3;
        #pragma unroll
        for (int i=0;i<2;i++){
            int row = (tid>>2) + 64*i;
            uint32_t h01,l01,h23,l23;
            split2(av[i].x, av[i].y, h01, l01);
            split2(av[i].z, av[i].w, h23, l23);
            int a = row*APAD2 + kq*2;
            *(uint2*)(Ah + a) = make_uint2(h01, h23);
            *(uint2*)(Al + a) = make_uint2(l01, l23);
        }
        {
            uint32_t h,l;
            split2(q00.x, q01.x, h, l); Bh[ n2   *BPAD2 + kp    ] = h; Bl[ n2   *BPAD2 + kp    ] = l;
            split2(q00.y, q01.y, h, l); Bh[(n2+1)*BPAD2 + kp    ] = h; Bl[(n2+1)*BPAD2 + kp    ] = l;
            split2(q10.x, q11.x, h, l); Bh[ n2   *BPAD2 + kp + 4] = h; Bl[ n2   *BPAD2 + kp + 4] = l;
            split2(q10.y, q11.y, h, l); Bh[(n2+1)*BPAD2 + kp + 4] = h; Bl[(n2+1)*BPAD2 + kp + 4] = l;
        }
    };

    float acc[4][4][4] = {};
    auto COMPUTE = [&](int b){
        char* bb = bufbase + b*BUF1_SZ;
        const uint32_t* Ah = (const uint32_t*)(bb + OFF_AH1);
        const uint32_t* Al = (const uint32_t*)(bb + OFF_AL1);
        const uint32_t* Bh = (const uint32_t*)(bb + OFF_BH1);
        const uint32_t* Bl = (const uint32_t*)(bb + OFF_BL1);
        uint32_t afh[4][4], afl[4][4];
        #pragma unroll
        for (int mf=0;mf<4;mf++){
            int r0 = mw + mf*16 + g, r1 = r0 + 8;
            afh[mf][0] = Ah[r0*APAD2 + tig];
            afh[mf][1] = Ah[r1*APAD2 + tig];
            afh[mf][2] = Ah[r0*APAD2 + tig + 4];
            afh[mf][3] = Ah[r1*APAD2 + tig + 4];
            afl[mf][0] = Al[r0*APAD2 + tig];
            afl[mf][1] = Al[r1*APAD2 + tig];
            afl[mf][2] = Al[r0*APAD2 + tig + 4];
            afl[mf][3] = Al[r1*APAD2 + tig + 4];
        }
        #pragma unroll
        for (int nf=0;nf<4;nf++){
            int n = nw + nf*8 + g;
            uint32_t bh0 = Bh[n*BPAD2 + tig];
            uint32_t bh1 = Bh[n*BPAD2 + tig + 4];
            uint32_t bl0 = Bl[n*BPAD2 + tig];
            uint32_t bl1 = Bl[n*BPAD2 + tig + 4];
            #pragma unroll
            for (int mf=0;mf<4;mf++){
                mma16(acc[mf][nf], afh[mf], bh0, bh1);   // hi*hi
                mma16(acc[mf][nf], afl[mf], bh0, bh1);   // lo*hi
                mma16(acc[mf][nf], afh[mf], bl0, bl1);   // hi*lo
            }
        }
    };

    LOADS(0);
    STORES(0);
    __syncthreads();
    for (int s=0;s<S;s++){
        if (s+1 < S) LOADS(s+1);
        COMPUTE(s&1);
        if (s+1 < S){
            STORES((s+1)&1);
            __syncthreads();
        }
    }

    // epilogue: gelu + split-write H (hi/lo half2, perm layout)
    #pragma unroll
    for (int mf=0;mf<4;mf++){
        int r0 = m0 + mw + mf*16 + g;
        int r1 = r0 + 8;
        #pragma unroll
        for (int nf=0;nf<4;nf++){
            int col = nw + nf*8 + tig*2;
            float b0 = biasp[col], b1 = biasp[col+1];
            uint32_t k2 = (uint32_t)(n0 + col) >> 1;
            uint32_t p = permk2(k2);
            if (r0 < cnt){
                float ox = gelu_tanh(acc[mf][nf][0] + b0);
                float oy = gelu_tanh(acc[mf][nf][1] + b1);
                uint32_t h,l; split2(ox, oy, h, l);
                g_Hh[(size_t)(off+r0)*(FDIM/2) + p] = h;
                g_Hl[(size_t)(off+r0)*(FDIM/2) + p] = l;
            }
            if (r1 < cnt){
                float ox = gelu_tanh(acc[mf][nf][2] + b0);
                float oy = gelu_tanh(acc[mf][nf][3] + b1);
                uint32_t h,l; split2(ox, oy, h, l);
                g_Hh[(size_t)(off+r1)*(FDIM/2) + p] = h;
                g_Hl[(size_t)(off+r1)*(FDIM/2) + p] = l;
            }
        }
    }
}

// ================= GEMM2: direct-global pre-split A (contiguous rows), split-K =================
#define OFF_BH2 0
#define OFF_BL2 8704
#define BUF2_SZ 17408
#define SM2_TOTAL (512 + 2*BUF2_SZ)

__global__ void __launch_bounds__(256, 2) gemm2_kernel(const float* __restrict__ W,
                                                       const float* __restrict__ bias){
    constexpr int KT  = FDIM;
    constexpr int K2  = KT/2;
    constexpr int LDW = DDIM;
    constexpr int S   = KT/16/KSPL;

    extern __shared__ char smem[];
    int* sidx = (int*)smem;
    char* bufbase = smem + 512;

    int e = blockIdx.z;
    int cnt = g_cnt[e];
    int my = blockIdx.y;
    int ks = my & (KSPL-1); my >>= 2;
    int m0 = my*128;
    if (m0 >= cnt) return;
    int off = g_off[e];
    int n0 = blockIdx.x*128;
    int kbase  = ks*(KT/KSPL);
    int kbase2 = kbase/2;
    int tid = threadIdx.x, w = tid>>5, lane = tid&31;
    int g = lane>>2, tig = lane&3;
    int mw = (w&1)*64, nw = (w>>1)*32;

    if (tid < 128){
        int i = m0 + tid; if (i >= cnt) i = cnt-1;
        sidx[tid] = off + i;
    }
    __syncthreads();

    uint32_t ro0[4], ro1[4];
    #pragma unroll
    for (int mf=0;mf<4;mf++){
        ro0[mf] = (uint32_t)sidx[mw + mf*16 + g]     * K2;
        ro1[mf] = (uint32_t)sidx[mw + mf*16 + g + 8] * K2;
    }

    int kp = tid>>6;
    int n2 = (tid&63)*2;
    const float* bptr = W + (size_t)e*KT*LDW + (size_t)kbase*LDW + n0 + n2;

    float2 q00, q01, q10, q11;
    auto LOADS = [&](int s){
        int k0 = s*16;
        q00 = *(const float2*)(bptr + (size_t)(k0 + 2*kp    )*LDW);
        q01 = *(const float2*)(bptr + (size_t)(k0 + 2*kp + 1)*LDW);
        q10 = *(const float2*)(bptr + (size_t)(k0 + 2*kp + 8)*LDW);
        q11 = *(const float2*)(bptr + (size_t)(k0 + 2*kp + 9)*LDW);
    };
    auto STORES = [&](int b){
        char* bb = bufbase + b*BUF2_SZ;
        uint32_t* Bh = (uint32_t*)(bb + OFF_BH2);
        uint32_t* Bl = (uint32_t*)(bb + OFF_BL2);
        uint32_t h,l;
        split2(q00.x, q01.x, h, l); Bh[ n2   *BPAD2 + kp    ] = h; Bl[ n2   *BPAD2 + kp    ] = l;
        split2(q00.y, q01.y, h, l); Bh[(n2+1)*BPAD2 + kp    ] = h; Bl[(n2+1)*BPAD2 + kp    ] = l;
        split2(q10.x, q11.x, h, l); Bh[ n2   *BPAD2 + kp + 4] = h; Bl[ n2   *BPAD2 + kp + 4] = l;
        split2(q10.y, q11.y, h, l); Bh[(n2+1)*BPAD2 + kp + 4] = h; Bl[(n2+1)*BPAD2 + kp + 4] = l;
    };

    float acc[4][4][4] = {};
    auto COMPUTE = [&](int b, int kk2){
        char* bb = bufbase + b*BUF2_SZ;
        const uint32_t* Bh = (const uint32_t*)(bb + OFF_BH2);
        const uint32_t* Bl = (const uint32_t*)(bb + OFF_BL2);
        uint32_t afh[4][4], afl[4][4];
        int ka = kk2 + tig*2;
        #pragma unroll
        for (int mf=0;mf<4;mf++){
            uint2 h0 = *(const uint2*)(g_Hh + ro0[mf] + ka);
            uint2 h1 = *(const uint2*)(g_Hh + ro1[mf] + ka);
            afh[mf][0]=h0.x; afh[mf][1]=h1.x; afh[mf][2]=h0.y; afh[mf][3]=h1.y;
            uint2 l0 = *(const uint2*)(g_Hl + ro0[mf] + ka);
            uint2 l1 = *(const uint2*)(g_Hl + ro1[mf] + ka);
            afl[mf][0]=l0.x; afl[mf][1]=l1.x; afl[mf][2]=l0.y; afl[mf][3]=l1.y;
        }
        #pragma unroll
        for (int nf=0;nf<4;nf++){
            int n = nw + nf*8 + g;
            uint32_t bh0 = Bh[n*BPAD2 + tig];
            uint32_t bh1 = Bh[n*BPAD2 + tig + 4];
            uint32_t bl0 = Bl[n*BPAD2 + tig];
            uint32_t bl1 = Bl[n*BPAD2 + tig + 4];
            #pragma unroll
            for (int mf=0;mf<4;mf++){
                mma16(acc[mf][nf], afh[mf], bh0, bh1);
                mma16(acc[mf][nf], afl[mf], bh0, bh1);
                mma16(acc[mf][nf], afh[mf], bl0, bl1);
            }
        }
    };

    LOADS(0);
    STORES(0);
    __syncthreads();
    for (int s=0;s<S;s++){
        if (s+1 < S) LOADS(s+1);
        COMPUTE(s&1, kbase2 + s*8);
        if (s+1 < S){
            STORES((s+1)&1);
            __syncthreads();
        }
    }

    float* Outp = g_Yp + (size_t)ks*RTOT*DDIM;
    #pragma unroll
    for (int mf=0;mf<4;mf++){
        int r0 = m0 + mw + mf*16 + g;
        int r1 = r0 + 8;
        #pragma unroll
        for (int nf=0;nf<4;nf++){
            int col = nw + nf*8 + tig*2;
            if (r0 < cnt)
                *(float2*)(Outp + (size_t)(off+r0)*LDW + n0 + col)
                    = make_float2(acc[mf][nf][0], acc[mf][nf][1]);
            if (r1 < cnt)
                *(float2*)(Outp + (size_t)(off+r1)*LDW + n0 + col)
                    = make_float2(acc[mf][nf][2], acc[mf][nf][3]);
        }
    }
}

// ---------------- combine: split-K reduction + bias + gated residual (+init on first) ----------------
__global__ void combine_kernel(float* __restrict__ out, const float* __restrict__ b2l,
                               const float* __restrict__ x, int first){
    int t = blockIdx.x, tid = threadIdx.x;
    int r1 = g_tok_row[t*2+0], r2 = g_tok_row[t*2+1];
    float g1 = g_topv[t*2+0],  g2 = g_topv[t*2+1];
    int e1 = g_topi[t*2+0],    e2 = g_topi[t*2+1];
    const float* p0 = g_Yp;
    #pragma unroll
    for (int q=0;q<4;q++){
        int d = q*256 + tid;
        float y1 = p0[((size_t)0*RTOT + r1)*DDIM + d]
                 + p0[((size_t)1*RTOT + r1)*DDIM + d]
                 + p0[((size_t)2*RTOT + r1)*DDIM + d]
                 + p0[((size_t)3*RTOT + r1)*DDIM + d]
                 + b2l[(size_t)e1*DDIM + d];
        float y2 = p0[((size_t)0*RTOT + r2)*DDIM + d]
                 + p0[((size_t)1*RTOT + r2)*DDIM + d]
                 + p0[((size_t)2*RTOT + r2)*DDIM + d]
                 + p0[((size_t)3*RTOT + r2)*DDIM + d]
                 + b2l[(size_t)e2*DDIM + d];
        float base = first ? x[(size_t)t*DDIM + d] : out[(size_t)t*DDIM + d];
        out[(size_t)t*DDIM + d] = base + g1*y1 + g2*y2;
    }
}
__global__ void finish_kernel(float* __restrict__ out){
    out[(size_t)NTOK*DDIM] = g_loss;
}

// ================= exact-recompute path (bitwise-R1 for flagged tokens) =================
__global__ void flist_kernel(){
    int t = blockIdx.x*blockDim.x + threadIdx.x;
    if (t < NTOK && g_flag[t]){
        int pos = atomicAdd(&g_F, 1);
        if (pos < MAXF) g_flist[pos] = t;
    }
}
__global__ void ex_init_kernel(const float* __restrict__ x){
    int b = blockIdx.x;
    if (b >= g_F || b >= MAXF) return;
    int t = g_flist[b], tid = threadIdx.x;
    #pragma unroll
    for (int q=0;q<4;q++)
        ex_x[b*DDIM + q*256 + tid] = x[(size_t)t*DDIM + q*256 + tid];
}
__global__ void ex_ln_kernel(){
    int b = blockIdx.x;
    if (b >= g_F || b >= MAXF) return;
    int tid = threadIdx.x;
    __shared__ float red[256];
    float v[4];
    #pragma unroll
    for (int q=0;q<4;q++) v[q] = ex_x[b*DDIM + q*256 + tid];
    float s = v[0]+v[1]+v[2]+v[3];
    red[tid]=s; __syncthreads();
    for (int o=128;o>0;o>>=1){ if(tid<o) red[tid]+=red[tid+o]; __syncthreads(); }
    float mean = red[0]*(1.0f/DDIM);
    __syncthreads();
    float s2=0.f;
    #pragma unroll
    for (int q=0;q<4;q++){ v[q]-=mean; s2 += v[q]*v[q]; }
    red[tid]=s2; __syncthreads();
    for (int o=128;o>0;o>>=1){ if(tid<o) red[tid]+=red[tid+o]; __syncthreads(); }
    float inv = 1.0f/sqrtf(red[0]*(1.0f/DDIM) + 1e-5f);
    #pragma unroll
    for (int q=0;q<4;q++) ex_xn[b*DDIM + q*256 + tid] = v[q]*inv;
}
__global__ void ex_router_kernel(const float* __restrict__ wr){
    int b = blockIdx.x;
    if (b >= g_F || b >= MAXF) return;
    int tid = threadIdx.x;
    __shared__ float sx[DDIM];
    __shared__ float slog[NEXP];
    #pragma unroll
    for (int q=0;q<4;q++) sx[q*256+tid] = ex_xn[b*DDIM + q*256 + tid];
    __syncthreads();
    int e = tid>>5, lane = tid&31;
    float acc = 0.f;
    for (int d=lane; d<DDIM; d+=32) acc += sx[d]*wr[d*NEXP+e];
    #pragma unroll
    for (int o=16;o>0;o>>=1) acc += __shfl_down_sync(0xffffffffu, acc, o);
    if (lane==0) slog[e]=acc;
    __syncthreads();
    if (tid==0){
        float p[NEXP];
        float m = slog[0];
        #pragma unroll
        for (int i=1;i<NEXP;i++) m = fmaxf(m, slog[i]);
        float ssum = 0.f;
        #pragma unroll
        for (int i=0;i<NEXP;i++){ p[i]=expf(slog[i]-m); ssum+=p[i]; }
        #pragma unroll
        for (int i=0;i<NEXP;i++) p[i] = p[i]/ssum;
        int i1=0; float v1=p[0];
        #pragma unroll
        for (int i=1;i<NEXP;i++) if (p[i]>v1){ v1=p[i]; i1=i; }
        int i2=-1; float v2=-1e30f;
        #pragma unroll
        for (int i=0;i<NEXP;i++) if (i!=i1 && p[i]>v2){ v2=p[i]; i2=i; }
        ex_topi[b*2+0]=i1; ex_topv[b*2+0]=v1;
        ex_topi[b*2+1]=i2; ex_topv[b*2+1]=v2;
    }
}
__global__ void ex_gemm1_kernel(const float* __restrict__ w1l, const float* __restrict__ b1l){
    int b = blockIdx.z;
    if (b >= g_F || b >= MAXF) return;
    int slot = blockIdx.y, tid = threadIdx.x;
    int col = blockIdx.x*256 + tid;
    int e = ex_topi[b*2+slot];
    __shared__ float sxn[DDIM];
    #pragma unroll
    for (int q=0;q<4;q++) sxn[q*256+tid] = ex_xn[b*DDIM + q*256 + tid];
    __syncthreads();
    const float* wcol = w1l + (size_t)e*DDIM*FDIM + col;
    float acc = 0.f;
    #pragma unroll 8
    for (int k=0;k<DDIM;k++) acc = fmaf(sxn[k], wcol[(size_t)k*FDIM], acc);
    float bb = b1l[(size_t)e*FDIM + col];
    ex_h[((size_t)b*2+slot)*FDIM + col] = gelu_tanh(acc + bb);
}
__global__ void ex_gemm2_kernel(const float* __restrict__ w2l, const float* __restrict__ b2l){
    int b = blockIdx.z;
    if (b >= g_F || b >= MAXF) return;
    int slot = blockIdx.y, tid = threadIdx.x;
    int col = blockIdx.x*256 + tid;
    int e = ex_topi[b*2+slot];
    __shared__ float sh[FDIM];
    #pragma unroll
    for (int q=0;q<16;q++) sh[q*256+tid] = ex_h[((size_t)b*2+slot)*FDIM + q*256 + tid];
    __syncthreads();
    const float* wcol = w2l + (size_t)e*FDIM*DDIM + col;
    float acc = 0.f;
    #pragma unroll 8
    for (int k=0;k<FDIM;k++) acc = fmaf(sh[k], wcol[(size_t)k*DDIM], acc);
    float bb = b2l[(size_t)e*DDIM + col];
    ex_y[((size_t)b*2+slot)*DDIM + col] = acc + bb;
}
__global__ void ex_combine_kernel(){
    int b = blockIdx.x;
    if (b >= g_F || b >= MAXF) return;
    int tid = threadIdx.x;
    float g1 = ex_topv[b*2+0], g2 = ex_topv[b*2+1];
    const float* y1 = ex_y + ((size_t)b*2+0)*DDIM;
    const float* y2 = ex_y + ((size_t)b*2+1)*DDIM;
    #pragma unroll
    for (int q=0;q<4;q++){
        int d = q*256 + tid;
        ex_x[b*DDIM + d] += g1*y1[d] + g2*y2[d];
    }
}
__global__ void ex_write_kernel(float* __restrict__ out){
    int b = blockIdx.x;
    if (b >= g_F || b >= MAXF) return;
    int t = g_flist[b], tid = threadIdx.x;
    #pragma unroll
    for (int q=0;q<4;q++)
        out[(size_t)t*DDIM + q*256 + tid] = ex_x[b*DDIM + q*256 + tid];
}

// ---------------- launch ----------------
extern "C" void kernel_launch(void* const* d_in, const int* in_sizes, int n_in,
                              void* d_out, int out_size){
    const float* x  = (const float*)d_in[0];
    const float* wr = (const float*)d_in[1];
    const float* w1 = (const float*)d_in[2];
    const float* b1 = (const float*)d_in[3];
    const float* w2 = (const float*)d_in[4];
    const float* b2 = (const float*)d_in[5];
    float* out = (float*)d_out;

    cudaFuncSetAttribute((const void*)gemm1_kernel, cudaFuncAttributeMaxDynamicSharedMemorySize, SM1_TOTAL);
    cudaFuncSetAttribute((const void*)gemm2_kernel, cudaFuncAttributeMaxDynamicSharedMemorySize, SM2_TOTAL);

    // fast path (4th launch overall == gemm2 for ncu capture)
    for (int l=0;l<NLAY;l++){
        const float* wr_l = wr + (size_t)l*DDIM*NEXP;
        const float* w1_l = w1 + (size_t)l*NEXP*DDIM*FDIM;
        const float* b1_l = b1 + (size_t)l*NEXP*FDIM;
        const float* w2_l = w2 + (size_t)l*NEXP*FDIM*DDIM;
        const float* b2_l = b2 + (size_t)l*NEXP*DDIM;
        int first = (l==0);

        lnrouter_kernel  <<<NTOK, 256>>>(first ? x : out, wr_l, first);
        statsplace_kernel<<<1, 1024>>>(first);
        gemm1_kernel<<<dim3(FDIM/128, 32, NEXP), 256, SM1_TOTAL>>>(w1_l, b1_l);
        gemm2_kernel<<<dim3(DDIM/128, 32*KSPL, NEXP), 256, SM2_TOTAL>>>(w2_l, b2_l);
        combine_kernel<<<NTOK, 256>>>(out, b2_l, x, first);
    }

    // exact recompute of flagged tokens (bitwise-R1)
    flist_kernel  <<<NTOK/256, 256>>>();
    ex_init_kernel<<<MAXF, 256>>>(x);
    for (int l=0;l<NLAY;l++){
        const float* wr_l = wr + (size_t)l*DDIM*NEXP;
        const float* w1_l = w1 + (size_t)l*NEXP*DDIM*FDIM;
        const float* b1_l = b1 + (size_t)l*NEXP*FDIM;
        const float* w2_l = w2 + (size_t)l*NEXP*FDIM*DDIM;
        const float* b2_l = b2 + (size_t)l*NEXP*DDIM;

        ex_ln_kernel    <<<MAXF, 256>>>();
        ex_router_kernel<<<MAXF, 256>>>(wr_l);
        ex_gemm1_kernel <<<dim3(FDIM/256, 2, MAXF), 256>>>(w1_l, b1_l);
        ex_gemm2_kernel <<<dim3(DDIM/256, 2, MAXF), 256>>>(w2_l, b2_l);
        ex_combine_kernel<<<MAXF, 256>>>();
    }
    ex_write_kernel<<<MAXF, 256>>>(out);

    if (out_size > NTOK*DDIM) finish_kernel<<<1,1>>>(out);
}

// round 16
// speedup vs baseline: 1.1013x; 1.0176x over previous
#include <cuda_runtime.h>
#include <cuda_fp16.h>
#include <math.h>
#include <stdint.h>

#define NTOK 2048
#define DDIM 1024
#define FDIM 4096
#define NEXP 8
#define NLAY 6
#define RTOT (NTOK*2)
#define MAXF 256
#define TAU  2e-4f
#define KSPL 4

// ---------------- scratch ----------------
__device__ float    g_xn[NTOK*DDIM];             // fp32 xn (gemm1 stages from here)
__device__ uint32_t g_Hx[(size_t)RTOT*FDIM];     // H split, interleaved hi/lo half2 (perm layout)
__device__ float g_probs[NTOK*NEXP];
__device__ int   g_topi[RTOT];
__device__ float g_topv[RTOT];
__device__ int   g_cnt[NEXP], g_off[NEXP];
__device__ int   g_row_tok[RTOT];
__device__ int   g_tok_row[RTOT];
__device__ float g_Yp[(size_t)KSPL*RTOT*DDIM];   // split-K partials for GEMM2
__device__ float g_loss;
// exact-recompute scratch
__device__ int   g_flag[NTOK];
__device__ int   g_flist[MAXF];
__device__ int   g_F;
__device__ float ex_x [MAXF*DDIM];
__device__ float ex_xn[MAXF*DDIM];
__device__ float ex_h [(size_t)MAXF*2*FDIM];
__device__ float ex_y [(size_t)MAXF*2*DDIM];
__device__ int   ex_topi[MAXF*2];
__device__ float ex_topv[MAXF*2];

__device__ __forceinline__ void mma16(float* d, const uint32_t* a, uint32_t b0, uint32_t b1){
    asm volatile("mma.sync.aligned.m16n8k16.row.col.f32.f16.f16.f32 "
        "{%0,%1,%2,%3}, {%4,%5,%6,%7}, {%8,%9}, {%0,%1,%2,%3};"
        : "+f"(d[0]), "+f"(d[1]), "+f"(d[2]), "+f"(d[3])
        : "r"(a[0]), "r"(a[1]), "r"(a[2]), "r"(a[3]), "r"(b0), "r"(b1));
}
__device__ __forceinline__ void split2(float x, float y, uint32_t& hi, uint32_t& lo){
    __half2 h = __floats2half2_rn(x, y);
    float hx = __low2float(h), hy = __high2float(h);
    __half2 l = __floats2half2_rn(x - hx, y - hy);
    hi = *reinterpret_cast<uint32_t*>(&h);
    lo = *reinterpret_cast<uint32_t*>(&l);
}
// permuted position within each 8-wide k2 group: fragment pairs (l, l+4) adjacent
__device__ __forceinline__ uint32_t permk2(uint32_t k2){
    return (k2 & ~7u) | (((k2 & 3u) << 1) | ((k2 >> 2) & 1u));
}
__device__ __forceinline__ float gelu_tanh(float x){
    float x3 = x*x*x;
    float t  = tanhf(0.7978845608028654f*(x + 0.044715f*x3));
    return 0.5f*x*(1.0f+t);
}

// ---------------- fused LN + router (margin flag; init fused via `first`) ----------------
__global__ void lnrouter_kernel(const float* __restrict__ xin, const float* __restrict__ wr,
                                int first){
    int t = blockIdx.x, tid = threadIdx.x;
    __shared__ float red[256];
    __shared__ float sx[DDIM];
    __shared__ float slog[NEXP];
    float v[4];
    #pragma unroll
    for (int q=0;q<4;q++) v[q] = xin[(size_t)t*DDIM + q*256 + tid];
    float s = v[0]+v[1]+v[2]+v[3];
    red[tid]=s; __syncthreads();
    for (int o=128;o>0;o>>=1){ if(tid<o) red[tid]+=red[tid+o]; __syncthreads(); }
    float mean = red[0]*(1.0f/DDIM);
    __syncthreads();
    float s2=0.f;
    #pragma unroll
    for (int q=0;q<4;q++){ v[q]-=mean; s2 += v[q]*v[q]; }
    red[tid]=s2; __syncthreads();
    for (int o=128;o>0;o>>=1){ if(tid<o) red[tid]+=red[tid+o]; __syncthreads(); }
    float inv = 1.0f/sqrtf(red[0]*(1.0f/DDIM) + 1e-5f);
    #pragma unroll
    for (int q=0;q<4;q++){
        float nv = v[q]*inv;
        g_xn[(size_t)t*DDIM + q*256 + tid] = nv;
        sx[q*256 + tid] = nv;
    }
    __syncthreads();
    int e = tid>>5, lane = tid&31;
    float acc = 0.f;
    for (int d=lane; d<DDIM; d+=32) acc += sx[d]*wr[d*NEXP+e];
    #pragma unroll
    for (int o=16;o>0;o>>=1) acc += __shfl_down_sync(0xffffffffu, acc, o);
    if (lane==0) slog[e]=acc;
    __syncthreads();
    if (tid==0){
        float p[NEXP];
        float m = slog[0];
        #pragma unroll
        for (int i=1;i<NEXP;i++) m = fmaxf(m, slog[i]);
        float ssum = 0.f;
        #pragma unroll
        for (int i=0;i<NEXP;i++){ p[i]=expf(slog[i]-m); ssum+=p[i]; }
        #pragma unroll
        for (int i=0;i<NEXP;i++){ p[i] = p[i]/ssum; g_probs[t*NEXP+i]=p[i]; }
        int i1=0; float v1=p[0];
        #pragma unroll
        for (int i=1;i<NEXP;i++) if (p[i]>v1){ v1=p[i]; i1=i; }
        int i2=-1; float v2=-1e30f;
        #pragma unroll
        for (int i=0;i<NEXP;i++) if (i!=i1 && p[i]>v2){ v2=p[i]; i2=i; }
        float v3=-1e30f;
        #pragma unroll
        for (int i=0;i<NEXP;i++) if (i!=i1 && i!=i2 && p[i]>v3) v3=p[i];
        int c = (v2 - v3 < TAU) ? 1 : 0;
        if (first) g_flag[t] = c;
        else if (c) g_flag[t] = 1;
        g_topi[t*2+0]=i1; g_topv[t*2+0]=v1;
        g_topi[t*2+1]=i2; g_topv[t*2+1]=v2;
    }
}

// ---------------- stats + placement (single block) ----------------
__global__ void statsplace_kernel(int first){
    int tid = threadIdx.x;                 // 1024 threads
    __shared__ int   sc[NEXP];
    __shared__ int   scur[NEXP];
    __shared__ int   soff[NEXP];
    __shared__ float red[1024];
    __shared__ float sexp[NEXP];
    if (tid<NEXP){ sc[tid]=0; scur[tid]=0; }
    __syncthreads();
    for (int i=tid;i<RTOT;i+=1024) atomicAdd(&sc[g_topi[i]], 1);
    float myp[NEXP];
    #pragma unroll
    for (int e=0;e<NEXP;e++) myp[e]=0.f;
    for (int t=tid;t<NTOK;t+=1024){
        #pragma unroll
        for (int e=0;e<NEXP;e++) myp[e] += g_probs[t*NEXP+e];
    }
    __syncthreads();
    for (int e=0;e<NEXP;e++){
        red[tid]=myp[e]; __syncthreads();
        for (int o=512;o>0;o>>=1){ if(tid<o) red[tid]+=red[tid+o]; __syncthreads(); }
        if (tid==0) sexp[e]=red[0];
        __syncthreads();
    }
    if (tid==0){
        float loss=0.f; int off=0;
        #pragma unroll
        for (int e=0;e<NEXP;e++){
            loss += ((float)sc[e]*(1.0f/NTOK)) * (sexp[e]*(1.0f/NTOK));
            g_cnt[e]=sc[e]; g_off[e]=off; soff[e]=off; off+=sc[e];
        }
        if (first){ g_loss = (float)NEXP*loss; g_F = 0; }
        else        g_loss += (float)NEXP*loss;
    }
    __syncthreads();
    for (int i=tid;i<RTOT;i+=1024){
        int e = g_topi[i];
        int r = soff[e] + atomicAdd(&scur[e], 1);
        g_row_tok[r] = i>>1;
        g_tok_row[i] = r;
    }
}

// ================= GEMM1: R13 SMEM-staged mainloop, interleaved split-H epilogue =================
#define APAD2 12
#define BPAD2 17
#define OFF_AH1 0
#define OFF_AL1 6144
#define OFF_BH1 12288
#define OFF_BL1 20992
#define BUF1_SZ 29696
#define SM1_TOTAL (512 + 2*BUF1_SZ)

__global__ void __launch_bounds__(256, 2) gemm1_kernel(const float* __restrict__ W,
                                                       const float* __restrict__ bias){
    constexpr int KT  = DDIM;
    constexpr int LDW = FDIM;
    constexpr int S   = KT/16;

    extern __shared__ char smem[];
    int* sidx = (int*)smem;
    char* bufbase = smem + 512;

    int e = blockIdx.z;
    int cnt = g_cnt[e];
    int m0 = blockIdx.y*128;
    if (m0 >= cnt) return;
    int off = g_off[e];
    int n0 = blockIdx.x*128;
    int tid = threadIdx.x, w = tid>>5, lane = tid&31;
    int g = lane>>2, tig = lane&3;
    int mw = (w&1)*64, nw = (w>>1)*32;

    if (tid < 128){
        int i = m0 + tid; if (i >= cnt) i = cnt-1;
        sidx[tid] = g_row_tok[off+i];
    }
    __syncthreads();

    const float* aptr0 = g_xn + (size_t)sidx[tid>>2]*KT + (tid&3)*4;
    const float* aptr1 = g_xn + (size_t)sidx[(tid>>2)+64]*KT + (tid&3)*4;
    int kp = tid>>6;
    int n2 = (tid&63)*2;
    const float* bptr = W + (size_t)e*KT*LDW + n0 + n2;
    const float* biasp = bias + (size_t)e*LDW + n0;

    float4 av[2];
    float2 q00, q01, q10, q11;
    auto LOADS = [&](int s){
        int k0 = s*16;
        av[0] = *(const float4*)(aptr0 + k0);
        av[1] = *(const float4*)(aptr1 + k0);
        q00 = *(const float2*)(bptr + (size_t)(k0 + 2*kp    )*LDW);
        q01 = *(const float2*)(bptr + (size_t)(k0 + 2*kp + 1)*LDW);
        q10 = *(const float2*)(bptr + (size_t)(k0 + 2*kp + 8)*LDW);
        q11 = *(const float2*)(bptr + (size_t)(k0 + 2*kp + 9)*LDW);
    };
    auto STORES = [&](int b){
        char* bb = bufbase + b*BUF1_SZ;
        uint32_t* Ah = (uint32_t*)(bb + OFF_AH1);
        uint32_t* Al = (uint32_t*)(bb + OFF_AL1);
        uint32_t* Bh = (uint32_t*)(bb + OFF_BH1);
        uint32_t* Bl = (uint32_t*)(bb + OFF_BL1);
        int kq = tid&3;
        #pragma unroll
        for (int i=0;i<2;i++){
            int row = (tid>>2) + 64*i;
            uint32_t h01,l01,h23,l23;
            split2(av[i].x, av[i].y, h01, l01);
            split2(av[i].z, av[i].w, h23, l23);
            int a = row*APAD2 + kq*2;
            *(uint2*)(Ah + a) = make_uint2(h01, h23);
            *(uint2*)(Al + a) = make_uint2(l01, l23);
        }
        {
            uint32_t h,l;
            split2(q00.x, q01.x, h, l); Bh[ n2   *BPAD2 + kp    ] = h; Bl[ n2   *BPAD2 + kp    ] = l;
            split2(q00.y, q01.y, h, l); Bh[(n2+1)*BPAD2 + kp    ] = h; Bl[(n2+1)*BPAD2 + kp    ] = l;
            split2(q10.x, q11.x, h, l); Bh[ n2   *BPAD2 + kp + 4] = h; Bl[ n2   *BPAD2 + kp + 4] = l;
            split2(q10.y, q11.y, h, l); Bh[(n2+1)*BPAD2 + kp + 4] = h; Bl[(n2+1)*BPAD2 + kp + 4] = l;
        }
    };

    float acc[4][4][4] = {};
    auto COMPUTE = [&](int b){
        char* bb = bufbase + b*BUF1_SZ;
        const uint32_t* Ah = (const uint32_t*)(bb + OFF_AH1);
        const uint32_t* Al = (const uint32_t*)(bb + OFF_AL1);
        const uint32_t* Bh = (const uint32_t*)(bb + OFF_BH1);
        const uint32_t* Bl = (const uint32_t*)(bb + OFF_BL1);
        uint32_t afh[4][4], afl[4][4];
        #pragma unroll
        for (int mf=0;mf<4;mf++){
            int r0 = mw + mf*16 + g, r1 = r0 + 8;
            afh[mf][0] = Ah[r0*APAD2 + tig];
            afh[mf][1] = Ah[r1*APAD2 + tig];
            afh[mf][2] = Ah[r0*APAD2 + tig + 4];
            afh[mf][3] = Ah[r1*APAD2 + tig + 4];
            afl[mf][0] = Al[r0*APAD2 + tig];
            afl[mf][1] = Al[r1*APAD2 + tig];
            afl[mf][2] = Al[r0*APAD2 + tig + 4];
            afl[mf][3] = Al[r1*APAD2 + tig + 4];
        }
        #pragma unroll
        for (int nf=0;nf<4;nf++){
            int n = nw + nf*8 + g;
            uint32_t bh0 = Bh[n*BPAD2 + tig];
            uint32_t bh1 = Bh[n*BPAD2 + tig + 4];
            uint32_t bl0 = Bl[n*BPAD2 + tig];
            uint32_t bl1 = Bl[n*BPAD2 + tig + 4];
            #pragma unroll
            for (int mf=0;mf<4;mf++){
                mma16(acc[mf][nf], afh[mf], bh0, bh1);   // hi*hi
                mma16(acc[mf][nf], afl[mf], bh0, bh1);   // lo*hi
                mma16(acc[mf][nf], afh[mf], bl0, bl1);   // hi*lo
            }
        }
    };

    LOADS(0);
    STORES(0);
    __syncthreads();
    for (int s=0;s<S;s++){
        if (s+1 < S) LOADS(s+1);
        COMPUTE(s&1);
        if (s+1 < S){
            STORES((s+1)&1);
            __syncthreads();
        }
    }

    // epilogue: gelu + split-write H, interleaved (uint2 = 8B per element pair, R13-grade coalescing)
    #pragma unroll
    for (int mf=0;mf<4;mf++){
        int r0 = m0 + mw + mf*16 + g;
        int r1 = r0 + 8;
        #pragma unroll
        for (int nf=0;nf<4;nf++){
            int col = nw + nf*8 + tig*2;
            float b0 = biasp[col], b1 = biasp[col+1];
            uint32_t k2 = (uint32_t)(n0 + col) >> 1;
            uint32_t c = 2u*permk2(k2);
            if (r0 < cnt){
                float ox = gelu_tanh(acc[mf][nf][0] + b0);
                float oy = gelu_tanh(acc[mf][nf][1] + b1);
                uint32_t h,l; split2(ox, oy, h, l);
                *(uint2*)(g_Hx + (size_t)(off+r0)*FDIM + c) = make_uint2(h, l);
            }
            if (r1 < cnt){
                float ox = gelu_tanh(acc[mf][nf][2] + b0);
                float oy = gelu_tanh(acc[mf][nf][3] + b1);
                uint32_t h,l; split2(ox, oy, h, l);
                *(uint2*)(g_Hx + (size_t)(off+r1)*FDIM + c) = make_uint2(h, l);
            }
        }
    }
}

// ================= GEMM2: direct-global interleaved split A (LDG.128), split-K =================
#define OFF_BH2 0
#define OFF_BL2 8704
#define BUF2_SZ 17408
#define SM2_TOTAL (512 + 2*BUF2_SZ)

__global__ void __launch_bounds__(256, 2) gemm2_kernel(const float* __restrict__ W,
                                                       const float* __restrict__ bias){
    constexpr int KT  = FDIM;
    constexpr int LDW = DDIM;
    constexpr int S   = KT/16/KSPL;

    extern __shared__ char smem[];
    int* sidx = (int*)smem;
    char* bufbase = smem + 512;

    int e = blockIdx.z;
    int cnt = g_cnt[e];
    int my = blockIdx.y;
    int ks = my & (KSPL-1); my >>= 2;
    int m0 = my*128;
    if (m0 >= cnt) return;
    int off = g_off[e];
    int n0 = blockIdx.x*128;
    int kbase  = ks*(KT/KSPL);
    int kbase2 = kbase/2;
    int tid = threadIdx.x, w = tid>>5, lane = tid&31;
    int g = lane>>2, tig = lane&3;
    int mw = (w&1)*64, nw = (w>>1)*32;

    if (tid < 128){
        int i = m0 + tid; if (i >= cnt) i = cnt-1;
        sidx[tid] = off + i;
    }
    __syncthreads();

    uint32_t ro0[4], ro1[4];
    #pragma unroll
    for (int mf=0;mf<4;mf++){
        ro0[mf] = (uint32_t)sidx[mw + mf*16 + g]     * FDIM;
        ro1[mf] = (uint32_t)sidx[mw + mf*16 + g + 8] * FDIM;
    }

    int kp = tid>>6;
    int n2 = (tid&63)*2;
    const float* bptr = W + (size_t)e*KT*LDW + (size_t)kbase*LDW + n0 + n2;

    float2 q00, q01, q10, q11;
    auto LOADS = [&](int s){
        int k0 = s*16;
        q00 = *(const float2*)(bptr + (size_t)(k0 + 2*kp    )*LDW);
        q01 = *(const float2*)(bptr + (size_t)(k0 + 2*kp + 1)*LDW);
        q10 = *(const float2*)(bptr + (size_t)(k0 + 2*kp + 8)*LDW);
        q11 = *(const float2*)(bptr + (size_t)(k0 + 2*kp + 9)*LDW);
    };
    auto STORES = [&](int b){
        char* bb = bufbase + b*BUF2_SZ;
        uint32_t* Bh = (uint32_t*)(bb + OFF_BH2);
        uint32_t* Bl = (uint32_t*)(bb + OFF_BL2);
        uint32_t h,l;
        split2(q00.x, q01.x, h, l); Bh[ n2   *BPAD2 + kp    ] = h; Bl[ n2   *BPAD2 + kp    ] = l;
        split2(q00.y, q01.y, h, l); Bh[(n2+1)*BPAD2 + kp    ] = h; Bl[(n2+1)*BPAD2 + kp    ] = l;
        split2(q10.x, q11.x, h, l); Bh[ n2   *BPAD2 + kp + 4] = h; Bl[ n2   *BPAD2 + kp + 4] = l;
        split2(q10.y, q11.y, h, l); Bh[(n2+1)*BPAD2 + kp + 4] = h; Bl[(n2+1)*BPAD2 + kp + 4] = l;
    };

    float acc[4][4][4] = {};
    auto COMPUTE = [&](int b, int kk2){
        char* bb = bufbase + b*BUF2_SZ;
        const uint32_t* Bh = (const uint32_t*)(bb + OFF_BH2);
        const uint32_t* Bl = (const uint32_t*)(bb + OFF_BL2);
        uint32_t afh[4][4], afl[4][4];
        uint32_t c = 2u*(uint32_t)kk2 + 4u*tig;
        #pragma unroll
        for (int mf=0;mf<4;mf++){
            uint4 v0 = *(const uint4*)(g_Hx + ro0[mf] + c);   // hi_k, lo_k, hi_k+8, lo_k+8
            uint4 v1 = *(const uint4*)(g_Hx + ro1[mf] + c);
            afh[mf][0]=v0.x; afl[mf][0]=v0.y; afh[mf][2]=v0.z; afl[mf][2]=v0.w;
            afh[mf][1]=v1.x; afl[mf][1]=v1.y; afh[mf][3]=v1.z; afl[mf][3]=v1.w;
        }
        #pragma unroll
        for (int nf=0;nf<4;nf++){
            int n = nw + nf*8 + g;
            uint32_t bh0 = Bh[n*BPAD2 + tig];
            uint32_t bh1 = Bh[n*BPAD2 + tig + 4];
            uint32_t bl0 = Bl[n*BPAD2 + tig];
            uint32_t bl1 = Bl[n*BPAD2 + tig + 4];
            #pragma unroll
            for (int mf=0;mf<4;mf++){
                mma16(acc[mf][nf], afh[mf], bh0, bh1);
                mma16(acc[mf][nf], afl[mf], bh0, bh1);
                mma16(acc[mf][nf], afh[mf], bl0, bl1);
            }
        }
    };

    LOADS(0);
    STORES(0);
    __syncthreads();
    for (int s=0;s<S;s++){
        if (s+1 < S) LOADS(s+1);
        COMPUTE(s&1, kbase2 + s*8);
        if (s+1 < S){
            STORES((s+1)&1);
            __syncthreads();
        }
    }

    float* Outp = g_Yp + (size_t)ks*RTOT*DDIM;
    #pragma unroll
    for (int mf=0;mf<4;mf++){
        int r0 = m0 + mw + mf*16 + g;
        int r1 = r0 + 8;
        #pragma unroll
        for (int nf=0;nf<4;nf++){
            int col = nw + nf*8 + tig*2;
            if (r0 < cnt)
                *(float2*)(Outp + (size_t)(off+r0)*LDW + n0 + col)
                    = make_float2(acc[mf][nf][0], acc[mf][nf][1]);
            if (r1 < cnt)
                *(float2*)(Outp + (size_t)(off+r1)*LDW + n0 + col)
                    = make_float2(acc[mf][nf][2], acc[mf][nf][3]);
        }
    }
}

// ---------------- combine: split-K reduction + bias + gated residual (+init on first) ----------------
__global__ void combine_kernel(float* __restrict__ out, const float* __restrict__ b2l,
                               const float* __restrict__ x, int first){
    int t = blockIdx.x, tid = threadIdx.x;
    int r1 = g_tok_row[t*2+0], r2 = g_tok_row[t*2+1];
    float g1 = g_topv[t*2+0],  g2 = g_topv[t*2+1];
    int e1 = g_topi[t*2+0],    e2 = g_topi[t*2+1];
    const float* p0 = g_Yp;
    #pragma unroll
    for (int q=0;q<4;q++){
        int d = q*256 + tid;
        float y1 = p0[((size_t)0*RTOT + r1)*DDIM + d]
                 + p0[((size_t)1*RTOT + r1)*DDIM + d]
                 + p0[((size_t)2*RTOT + r1)*DDIM + d]
                 + p0[((size_t)3*RTOT + r1)*DDIM + d]
                 + b2l[(size_t)e1*DDIM + d];
        float y2 = p0[((size_t)0*RTOT + r2)*DDIM + d]
                 + p0[((size_t)1*RTOT + r2)*DDIM + d]
                 + p0[((size_t)2*RTOT + r2)*DDIM + d]
                 + p0[((size_t)3*RTOT + r2)*DDIM + d]
                 + b2l[(size_t)e2*DDIM + d];
        float base = first ? x[(size_t)t*DDIM + d] : out[(size_t)t*DDIM + d];
        out[(size_t)t*DDIM + d] = base + g1*y1 + g2*y2;
    }
}
__global__ void finish_kernel(float* __restrict__ out){
    out[(size_t)NTOK*DDIM] = g_loss;
}

// ================= exact-recompute path (bitwise-R1 for flagged tokens) =================
__global__ void flist_kernel(){
    int t = blockIdx.x*blockDim.x + threadIdx.x;
    if (t < NTOK && g_flag[t]){
        int pos = atomicAdd(&g_F, 1);
        if (pos < MAXF) g_flist[pos] = t;
    }
}
__global__ void ex_init_kernel(const float* __restrict__ x){
    int b = blockIdx.x;
    if (b >= g_F || b >= MAXF) return;
    int t = g_flist[b], tid = threadIdx.x;
    #pragma unroll
    for (int q=0;q<4;q++)
        ex_x[b*DDIM + q*256 + tid] = x[(size_t)t*DDIM + q*256 + tid];
}
__global__ void ex_ln_kernel(){
    int b = blockIdx.x;
    if (b >= g_F || b >= MAXF) return;
    int tid = threadIdx.x;
    __shared__ float red[256];
    float v[4];
    #pragma unroll
    for (int q=0;q<4;q++) v[q] = ex_x[b*DDIM + q*256 + tid];
    float s = v[0]+v[1]+v[2]+v[3];
    red[tid]=s; __syncthreads();
    for (int o=128;o>0;o>>=1){ if(tid<o) red[tid]+=red[tid+o]; __syncthreads(); }
    float mean = red[0]*(1.0f/DDIM);
    __syncthreads();
    float s2=0.f;
    #pragma unroll
    for (int q=0;q<4;q++){ v[q]-=mean; s2 += v[q]*v[q]; }
    red[tid]=s2; __syncthreads();
    for (int o=128;o>0;o>>=1){ if(tid<o) red[tid]+=red[tid+o]; __syncthreads(); }
    float inv = 1.0f/sqrtf(red[0]*(1.0f/DDIM) + 1e-5f);
    #pragma unroll
    for (int q=0;q<4;q++) ex_xn[b*DDIM + q*256 + tid] = v[q]*inv;
}
__global__ void ex_router_kernel(const float* __restrict__ wr){
    int b = blockIdx.x;
    if (b >= g_F || b >= MAXF) return;
    int tid = threadIdx.x;
    __shared__ float sx[DDIM];
    __shared__ float slog[NEXP];
    #pragma unroll
    for (int q=0;q<4;q++) sx[q*256+tid] = ex_xn[b*DDIM + q*256 + tid];
    __syncthreads();
    int e = tid>>5, lane = tid&31;
    float acc = 0.f;
    for (int d=lane; d<DDIM; d+=32) acc += sx[d]*wr[d*NEXP+e];
    #pragma unroll
    for (int o=16;o>0;o>>=1) acc += __shfl_down_sync(0xffffffffu, acc, o);
    if (lane==0) slog[e]=acc;
    __syncthreads();
    if (tid==0){
        float p[NEXP];
        float m = slog[0];
        #pragma unroll
        for (int i=1;i<NEXP;i++) m = fmaxf(m, slog[i]);
        float ssum = 0.f;
        #pragma unroll
        for (int i=0;i<NEXP;i++){ p[i]=expf(slog[i]-m); ssum+=p[i]; }
        #pragma unroll
        for (int i=0;i<NEXP;i++) p[i] = p[i]/ssum;
        int i1=0; float v1=p[0];
        #pragma unroll
        for (int i=1;i<NEXP;i++) if (p[i]>v1){ v1=p[i]; i1=i; }
        int i2=-1; float v2=-1e30f;
        #pragma unroll
        for (int i=0;i<NEXP;i++) if (i!=i1 && p[i]>v2){ v2=p[i]; i2=i; }
        ex_topi[b*2+0]=i1; ex_topv[b*2+0]=v1;
        ex_topi[b*2+1]=i2; ex_topv[b*2+1]=v2;
    }
}
__global__ void ex_gemm1_kernel(const float* __restrict__ w1l, const float* __restrict__ b1l){
    int b = blockIdx.z;
    if (b >= g_F || b >= MAXF) return;
    int slot = blockIdx.y, tid = threadIdx.x;
    int col = blockIdx.x*256 + tid;
    int e = ex_topi[b*2+slot];
    __shared__ float sxn[DDIM];
    #pragma unroll
    for (int q=0;q<4;q++) sxn[q*256+tid] = ex_xn[b*DDIM + q*256 + tid];
    __syncthreads();
    const float* wcol = w1l + (size_t)e*DDIM*FDIM + col;
    float acc = 0.f;
    #pragma unroll 8
    for (int k=0;k<DDIM;k++) acc = fmaf(sxn[k], wcol[(size_t)k*FDIM], acc);
    float bb = b1l[(size_t)e*FDIM + col];
    ex_h[((size_t)b*2+slot)*FDIM + col] = gelu_tanh(acc + bb);
}
__global__ void ex_gemm2_kernel(const float* __restrict__ w2l, const float* __restrict__ b2l){
    int b = blockIdx.z;
    if (b >= g_F || b >= MAXF) return;
    int slot = blockIdx.y, tid = threadIdx.x;
    int col = blockIdx.x*256 + tid;
    int e = ex_topi[b*2+slot];
    __shared__ float sh[FDIM];
    #pragma unroll
    for (int q=0;q<16;q++) sh[q*256+tid] = ex_h[((size_t)b*2+slot)*FDIM + q*256 + tid];
    __syncthreads();
    const float* wcol = w2l + (size_t)e*FDIM*DDIM + col;
    float acc = 0.f;
    #pragma unroll 8
    for (int k=0;k<FDIM;k++) acc = fmaf(sh[k], wcol[(size_t)k*DDIM], acc);
    float bb = b2l[(size_t)e*DDIM + col];
    ex_y[((size_t)b*2+slot)*DDIM + col] = acc + bb;
}
__global__ void ex_combine_kernel(){
    int b = blockIdx.x;
    if (b >= g_F || b >= MAXF) return;
    int tid = threadIdx.x;
    float g1 = ex_topv[b*2+0], g2 = ex_topv[b*2+1];
    const float* y1 = ex_y + ((size_t)b*2+0)*DDIM;
    const float* y2 = ex_y + ((size_t)b*2+1)*DDIM;
    #pragma unroll
    for (int q=0;q<4;q++){
        int d = q*256 + tid;
        ex_x[b*DDIM + d] += g1*y1[d] + g2*y2[d];
    }
}
__global__ void ex_write_kernel(float* __restrict__ out){
    int b = blockIdx.x;
    if (b >= g_F || b >= MAXF) return;
    int t = g_flist[b], tid = threadIdx.x;
    #pragma unroll
    for (int q=0;q<4;q++)
        out[(size_t)t*DDIM + q*256 + tid] = ex_x[b*DDIM + q*256 + tid];
}

// ---------------- launch ----------------
extern "C" void kernel_launch(void* const* d_in, const int* in_sizes, int n_in,
                              void* d_out, int out_size){
    const float* x  = (const float*)d_in[0];
    const float* wr = (const float*)d_in[1];
    const float* w1 = (const float*)d_in[2];
    const float* b1 = (const float*)d_in[3];
    const float* w2 = (const float*)d_in[4];
    const float* b2 = (const float*)d_in[5];
    float* out = (float*)d_out;

    cudaFuncSetAttribute((const void*)gemm1_kernel, cudaFuncAttributeMaxDynamicSharedMemorySize, SM1_TOTAL);
    cudaFuncSetAttribute((const void*)gemm2_kernel, cudaFuncAttributeMaxDynamicSharedMemorySize, SM2_TOTAL);

    // fast path (4th launch overall == gemm2 for ncu capture)
    for (int l=0;l<NLAY;l++){
        const float* wr_l = wr + (size_t)l*DDIM*NEXP;
        const float* w1_l = w1 + (size_t)l*NEXP*DDIM*FDIM;
        const float* b1_l = b1 + (size_t)l*NEXP*FDIM;
        const float* w2_l = w2 + (size_t)l*NEXP*FDIM*DDIM;
        const float* b2_l = b2 + (size_t)l*NEXP*DDIM;
        int first = (l==0);

        lnrouter_kernel  <<<NTOK, 256>>>(first ? x : out, wr_l, first);
        statsplace_kernel<<<1, 1024>>>(first);
        gemm1_kernel<<<dim3(FDIM/128, 32, NEXP), 256, SM1_TOTAL>>>(w1_l, b1_l);
        gemm2_kernel<<<dim3(DDIM/128, 32*KSPL, NEXP), 256, SM2_TOTAL>>>(w2_l, b2_l);
        combine_kernel<<<NTOK, 256>>>(out, b2_l, x, first);
    }

    // exact recompute of flagged tokens (bitwise-R1)
    flist_kernel  <<<NTOK/256, 256>>>();
    ex_init_kernel<<<MAXF, 256>>>(x);
    for (int l=0;l<NLAY;l++){
        const float* wr_l = wr + (size_t)l*DDIM*NEXP;
        const float* w1_l = w1 + (size_t)l*NEXP*DDIM*FDIM;
        const float* b1_l = b1 + (size_t)l*NEXP*FDIM;
        const float* w2_l = w2 + (size_t)l*NEXP*FDIM*DDIM;
        const float* b2_l = b2 + (size_t)l*NEXP*DDIM;

        ex_ln_kernel    <<<MAXF, 256>>>();
        ex_router_kernel<<<MAXF, 256>>>(wr_l);
        ex_gemm1_kernel <<<dim3(FDIM/256, 2, MAXF), 256>>>(w1_l, b1_l);
        ex_gemm2_kernel <<<dim3(DDIM/256, 2, MAXF), 256>>>(w2_l, b2_l);
        ex_combine_kernel<<<MAXF, 256>>>();
    }
    ex_write_kernel<<<MAXF, 256>>>(out);

    if (out_size > NTOK*DDIM) finish_kernel<<<1,1>>>(out);
}